// round 15
// baseline (speedup 1.0000x reference)
#include <cuda_runtime.h>
#include <cuda_fp16.h>
#include <cstdint>
#include <math.h>

#define BATCH 32
#define LQ    1024
#define LK    1024
#define HID   1024
#define KDIM  1024

// ---------------------------------------------------------------------------
// Device scratch (BSS). +128 pad rows where GEMM tile tails can read past the
// live region (all-selected corner case).
// ---------------------------------------------------------------------------
#define QN   ((size_t)BATCH * LQ * KDIM)
#define QNP  (QN + (size_t)128 * KDIM)
#define WN   ((size_t)HID * KDIM)
__device__ __half g_qh[QNP],  g_ql[QNP];
__device__ __half g_kh[QNP],  g_kl[QNP];
__device__ __half g_wqh[WN],  g_wql[WN];
__device__ __half g_wkh[WN],  g_wkl[WN];
__device__ __half g_qph[QNP], g_qpl[QNP];
__device__ __half g_kph[QNP], g_kpl[QNP];
__device__ float  g_logc[QN];
__device__ int    g_qidx[BATCH * LQ];
__device__ int    g_kidx[BATCH * LK];
__device__ int    g_qcnt[BATCH];
__device__ int    g_kcnt[BATCH];
__device__ int    g_qoff[BATCH + 1];
__device__ int    g_koff[BATCH + 1];

// ---------------------------------------------------------------------------
// PTX helpers (portable compute_103 ISA)
// ---------------------------------------------------------------------------
__device__ __forceinline__ uint32_t smem_u32(const void* p) {
    uint32_t a;
    asm("{ .reg .u64 t; cvta.to.shared.u64 t, %1; cvt.u32.u64 %0, t; }"
        : "=r"(a) : "l"(p));
    return a;
}

#define CP16(smem, gmem) \
    asm volatile("cp.async.cg.shared.global [%0], [%1], 16;" \
                 :: "r"(smem), "l"(gmem))
#define CP_COMMIT() asm volatile("cp.async.commit_group;" ::: "memory")
#define CP_WAIT2()  asm volatile("cp.async.wait_group 2;" ::: "memory")

#define LDSM4(r, addr) \
    asm volatile("ldmatrix.sync.aligned.m8n8.x4.shared.b16 {%0,%1,%2,%3}, [%4];" \
        : "=r"((r)[0]), "=r"((r)[1]), "=r"((r)[2]), "=r"((r)[3]) : "r"(addr))

#define MMA16816(d, a, b0, b1) \
    asm volatile("mma.sync.aligned.m16n8k16.row.col.f32.f16.f16.f32 " \
        "{%0,%1,%2,%3}, {%4,%5,%6,%7}, {%8,%9}, {%0,%1,%2,%3};" \
        : "+f"((d)[0]), "+f"((d)[1]), "+f"((d)[2]), "+f"((d)[3]) \
        : "r"((a)[0]), "r"((a)[1]), "r"((a)[2]), "r"((a)[3]), \
          "r"(b0), "r"(b1))

#define MMA16816F16(d, a, b0, b1) \
    asm volatile("mma.sync.aligned.m16n8k16.row.col.f16.f16.f16.f16 " \
        "{%0,%1}, {%2,%3,%4,%5}, {%6,%7}, {%0,%1};" \
        : "+r"((d)[0]), "+r"((d)[1]) \
        : "r"((a)[0]), "r"((a)[1]), "r"((a)[2]), "r"((a)[3]), \
          "r"(b0), "r"(b1))

// ---------------------------------------------------------------------------
// Deterministic mask partition per batch (Hillis-Steele scan).
// ---------------------------------------------------------------------------
__global__ void __launch_bounds__(1024) mask_scan_kernel(
    const int* __restrict__ qmask, const int* __restrict__ kmask,
    int* __restrict__ qidx, int* __restrict__ kidx,
    int* __restrict__ qcnt, int* __restrict__ kcnt)
{
    const int b = blockIdx.x;
    const int t = threadIdx.x;
    __shared__ int ps[1024];

#pragma unroll 1
    for (int pass = 0; pass < 2; pass++) {
        const int* mask = pass == 0 ? qmask : kmask;
        int*       idx  = pass == 0 ? qidx  : kidx;
        int*       cnt  = pass == 0 ? qcnt  : kcnt;
        const int m = mask[b * 1024 + t] != 0 ? 1 : 0;
        ps[t] = m;
        __syncthreads();
#pragma unroll
        for (int off = 1; off < 1024; off <<= 1) {
            int v = (t >= off) ? ps[t - off] : 0;
            __syncthreads();
            ps[t] += v;
            __syncthreads();
        }
        const int total = ps[1023];
        if (m) idx[b * 1024 + ps[t] - 1] = t;
        else   idx[b * 1024 + total + (t - ps[t])] = t;
        if (t == 0) cnt[b] = total;
        __syncthreads();
    }
}

__global__ void offsets_kernel(const int* __restrict__ qcnt,
                               const int* __restrict__ kcnt,
                               int* __restrict__ qoff, int* __restrict__ koff)
{
    if (threadIdx.x == 0) {
        int s = 0;
        for (int b = 0; b < BATCH; b++) { qoff[b] = s; s += qcnt[b]; }
        qoff[BATCH] = s;
    }
    if (threadIdx.x == 1) {
        int s = 0;
        for (int b = 0; b < BATCH; b++) { koff[b] = s; s += kcnt[b]; }
        koff[BATCH] = s;
    }
}

// ---------------------------------------------------------------------------
// Merged gather-split: z=0 -> query, z=1 -> key. Selected rows only, globally
// compacted. Block = one candidate row.
// ---------------------------------------------------------------------------
__global__ void __launch_bounds__(256) split_gather2_kernel(
    const float* __restrict__ x0, const int* __restrict__ idx0,
    const int* __restrict__ cnt0, const int* __restrict__ off0,
    __half* __restrict__ h0o, __half* __restrict__ l0o,
    const float* __restrict__ x1, const int* __restrict__ idx1,
    const int* __restrict__ cnt1, const int* __restrict__ off1,
    __half* __restrict__ h1o, __half* __restrict__ l1o)
{
    const int z = blockIdx.z;
    const float* x   = z ? x1   : x0;
    const int*   idx = z ? idx1 : idx0;
    const int*   cnt = z ? cnt1 : cnt0;
    const int*   off = z ? off1 : off0;
    __half* h = z ? h1o : h0o;
    __half* l = z ? l1o : l0o;

    const int b = blockIdx.y;
    const int i = blockIdx.x;
    if (i >= cnt[b]) return;
    const int t = threadIdx.x;
    const int src = idx[b * 1024 + i];
    const float* srow = x + ((long)b * 1024 + src) * 1024;
    const long drow = (long)(off[b] + i) * 1024;

    float4 v = ((const float4*)srow)[t];
    __half h0 = __float2half(v.x);
    __half h1 = __float2half(v.y);
    __half h2 = __float2half(v.z);
    __half h3 = __float2half(v.w);
    __half l0 = __float2half(v.x - __half2float(h0));
    __half l1 = __float2half(v.y - __half2float(h1));
    __half l2 = __float2half(v.z - __half2float(h2));
    __half l3 = __float2half(v.w - __half2float(h3));
    __half2* hp = (__half2*)(h + drow + (size_t)t * 4);
    __half2* lp = (__half2*)(l + drow + (size_t)t * 4);
    hp[0] = __halves2half2(h0, h1);
    hp[1] = __halves2half2(h2, h3);
    lp[0] = __halves2half2(l0, l1);
    lp[1] = __halves2half2(l2, l3);
}

// Plain split for the weights.
__global__ void __launch_bounds__(256) split_kernel(
    const float* __restrict__ x0, __half* __restrict__ h0o, __half* __restrict__ l0o,
    const float* __restrict__ x1, __half* __restrict__ h1o, __half* __restrict__ l1o,
    int n4)
{
    const float* x = (blockIdx.y == 0) ? x0 : x1;
    __half* h = (blockIdx.y == 0) ? h0o : h1o;
    __half* l = (blockIdx.y == 0) ? l0o : l1o;
    int i = blockIdx.x * 256 + threadIdx.x;
    if (i >= n4) return;
    float4 v = ((const float4*)x)[i];
    __half h0 = __float2half(v.x);
    __half h1 = __float2half(v.y);
    __half h2 = __float2half(v.z);
    __half h3 = __float2half(v.w);
    __half l0 = __float2half(v.x - __half2float(h0));
    __half l1 = __float2half(v.y - __half2float(h1));
    __half l2 = __float2half(v.z - __half2float(h2));
    __half l3 = __float2half(v.w - __half2float(h3));
    __half2* hp = (__half2*)(h + (size_t)i * 4);
    __half2* lp = (__half2*)(l + (size_t)i * 4);
    hp[0] = __halves2half2(h0, h1);
    hp[1] = __halves2half2(h2, h3);
    lp[0] = __halves2half2(l0, l1);
    lp[1] = __halves2half2(l2, l3);
}

// ---------------------------------------------------------------------------
// GEMM core body (round-14 champion): shared by both kernels below via macro.
// Computes acc/accx for A[abase+m0 .. +128) x B[bbase+n0 .. +128) over K.
// ---------------------------------------------------------------------------
#define STG_BYTES 40960u
#define SMEM_BYTES (4u * STG_BYTES)

#define GEMM_MAINLOOP(gAh, gAl, gBh, gBl, K)                                  \
    const int lr = tid >> 2;                                                  \
    const int lc = tid & 3;                                                   \
    const uint32_t srow = (uint32_t)(lr * 80 + lc * 16);                      \
    (void)srow;                                                               \
    const int warpM = (wid >> 2) * 32;                                        \
    const int warpN = (wid & 3) * 32;                                         \
    const uint32_t aoff = (uint32_t)((warpM + (l & 15)) * 80 + (l >> 4) * 16);\
    const uint32_t boff = (uint32_t)((warpN + (l & 7) + ((l >> 4) << 3)) * 80 \
                                     + (((l >> 3) & 1) ? 16 : 0));            \
    auto load_stage = [&](int stage, int k0) {                                \
        const uint32_t s = sb + (uint32_t)stage * STG_BYTES + srow;           \
        CP16(s,         gAh + k0);                                            \
        CP16(s + 10240, gAl + k0);                                            \
        CP16(s + 20480, gBh + k0);                                            \
        CP16(s + 30720, gBl + k0);                                            \
    };                                                                        \
    float acc[2][4][4];                                                       \
    uint32_t accx[2][4][2];                                                   \
    _Pragma("unroll")                                                         \
    for (int i = 0; i < 2; i++)                                               \
        _Pragma("unroll")                                                     \
        for (int j = 0; j < 4; j++) {                                         \
            _Pragma("unroll")                                                 \
            for (int r = 0; r < 4; r++) acc[i][j][r] = 0.0f;                  \
            accx[i][j][0] = 0u; accx[i][j][1] = 0u;                           \
        }                                                                     \
    const int NK = (K) >> 5;                                                  \
    load_stage(0, 0);  CP_COMMIT();                                           \
    load_stage(1, 32); CP_COMMIT();                                           \
    load_stage(2, 64); CP_COMMIT();                                           \
    for (int t = 0; t < NK; t++) {                                            \
        CP_WAIT2();                                                           \
        __syncthreads();                                                      \
        const int tn3 = t + 3;                                                \
        if (tn3 < NK) load_stage(tn3 & 3, tn3 * 32);                          \
        CP_COMMIT();                                                          \
        const uint32_t sbase = sb + (uint32_t)(t & 3) * STG_BYTES;            \
        _Pragma("unroll")                                                     \
        for (int ks = 0; ks < 2; ks++) {                                      \
            uint32_t ah[2][4], al[2][4], bh[2][4], bl[2][4];                  \
            _Pragma("unroll")                                                 \
            for (int mt = 0; mt < 2; mt++)                                    \
                LDSM4(ah[mt], sbase + aoff + mt * 1280 + ks * 32);            \
            _Pragma("unroll")                                                 \
            for (int np = 0; np < 2; np++)                                    \
                LDSM4(bh[np], sbase + 20480 + boff + np * 1280 + ks * 32);    \
            _Pragma("unroll")                                                 \
            for (int mt = 0; mt < 2; mt++)                                    \
                _Pragma("unroll")                                             \
                for (int nt = 0; nt < 4; nt++)                                \
                    MMA16816(acc[mt][nt], ah[mt],                             \
                             bh[nt >> 1][(nt & 1) * 2],                       \
                             bh[nt >> 1][(nt & 1) * 2 + 1]);                  \
            _Pragma("unroll")                                                 \
            for (int mt = 0; mt < 2; mt++)                                    \
                LDSM4(al[mt], sbase + 10240 + aoff + mt * 1280 + ks * 32);    \
            _Pragma("unroll")                                                 \
            for (int np = 0; np < 2; np++)                                    \
                LDSM4(bl[np], sbase + 30720 + boff + np * 1280 + ks * 32);    \
            _Pragma("unroll")                                                 \
            for (int mt = 0; mt < 2; mt++)                                    \
                _Pragma("unroll")                                             \
                for (int nt = 0; nt < 4; nt++)                                \
                    MMA16816F16(accx[mt][nt], ah[mt],                         \
                                bl[nt >> 1][(nt & 1) * 2],                    \
                                bl[nt >> 1][(nt & 1) * 2 + 1]);               \
            _Pragma("unroll")                                                 \
            for (int mt = 0; mt < 2; mt++)                                    \
                _Pragma("unroll")                                             \
                for (int nt = 0; nt < 4; nt++)                                \
                    MMA16816F16(accx[mt][nt], al[mt],                         \
                                bh[nt >> 1][(nt & 1) * 2],                    \
                                bh[nt >> 1][(nt & 1) * 2 + 1]);               \
        }                                                                     \
    }

// ---------------------------------------------------------------------------
// Merged projection GEMM: z=0 -> q-proj, z=1 -> k-proj. Grid (8, 256, 2).
// relu(acc+bias) re-split hi/lo into compacted outputs.
// ---------------------------------------------------------------------------
__global__ void __launch_bounds__(512, 1) gemm_proj_dual_kernel(
    const __half* __restrict__ Ah0, const __half* __restrict__ Al0,
    const __half* __restrict__ Wh0, const __half* __restrict__ Wl0,
    const float* __restrict__ bias0,
    __half* __restrict__ Ch0, __half* __restrict__ Cl0,
    const int* __restrict__ tot0,
    const __half* __restrict__ Ah1, const __half* __restrict__ Al1,
    const __half* __restrict__ Wh1, const __half* __restrict__ Wl1,
    const float* __restrict__ bias1,
    __half* __restrict__ Ch1, __half* __restrict__ Cl1,
    const int* __restrict__ tot1,
    int K, int N)
{
    extern __shared__ char smraw[];
    const uint32_t sb = smem_u32(smraw);
    const int tid = threadIdx.x;
    const int wid = tid >> 5;
    const int l   = tid & 31;

    const int z = blockIdx.z;
    const long m0 = (long)blockIdx.y * 128;
    const long n0 = (long)blockIdx.x * 128;
    const int tot = z ? *tot1 : *tot0;
    if (m0 >= tot) return;

    const __half* Ah  = z ? Ah1 : Ah0;
    const __half* Al  = z ? Al1 : Al0;
    const __half* Bh  = z ? Wh1 : Wh0;
    const __half* Bl  = z ? Wl1 : Wl0;
    const float* bias = z ? bias1 : bias0;
    __half* Ch = z ? Ch1 : Ch0;
    __half* Cl = z ? Cl1 : Cl0;

    const int lr_ = tid >> 2;
    const int lc_ = tid & 3;
    const __half* gAh = Ah + (m0 + lr_) * (long)K + lc_ * 8;
    const __half* gAl = Al + (m0 + lr_) * (long)K + lc_ * 8;
    const __half* gBh = Bh + (n0 + lr_) * (long)K + lc_ * 8;
    const __half* gBl = Bl + (n0 + lr_) * (long)K + lc_ * 8;

    GEMM_MAINLOOP(gAh, gAl, gBh, gBl, K)

    const int tm = l >> 2;
    const int tn = (l & 3) * 2;
#pragma unroll
    for (int mt = 0; mt < 2; mt++) {
        const long r0 = m0 + warpM + mt * 16 + tm;
        const long r1 = r0 + 8;
#pragma unroll
        for (int nt = 0; nt < 4; nt++) {
            const long col = n0 + warpN + nt * 8 + tn;
            float2 x01 = __half22float2(*(__half2*)&accx[mt][nt][0]);
            float2 x23 = __half22float2(*(__half2*)&accx[mt][nt][1]);
            float c0 = acc[mt][nt][0] + x01.x;
            float c1 = acc[mt][nt][1] + x01.y;
            float c2 = acc[mt][nt][2] + x23.x;
            float c3 = acc[mt][nt][3] + x23.y;
            const float b0 = bias[col], b1 = bias[col + 1];
            float v0 = fmaxf(c0 + b0, 0.0f);
            float v1 = fmaxf(c1 + b1, 0.0f);
            float v2 = fmaxf(c2 + b0, 0.0f);
            float v3 = fmaxf(c3 + b1, 0.0f);
            __half h0 = __float2half(v0), h1 = __float2half(v1);
            __half h2 = __float2half(v2), h3 = __float2half(v3);
            __half e0 = __float2half(v0 - __half2float(h0));
            __half e1 = __float2half(v1 - __half2float(h1));
            __half e2 = __float2half(v2 - __half2float(h2));
            __half e3 = __float2half(v3 - __half2float(h3));
            *(__half2*)(Ch + r0 * (long)N + col) = __halves2half2(h0, h1);
            *(__half2*)(Ch + r1 * (long)N + col) = __halves2half2(h2, h3);
            *(__half2*)(Cl + r0 * (long)N + col) = __halves2half2(e0, e1);
            *(__half2*)(Cl + r1 * (long)N + col) = __halves2half2(e2, e3);
        }
    }
}

// ---------------------------------------------------------------------------
// Batched compacted logits GEMM (unchanged from round 14).
// ---------------------------------------------------------------------------
__global__ void __launch_bounds__(512, 1) gemm_logits_kernel(
    const __half* __restrict__ Ah, const __half* __restrict__ Al,
    const __half* __restrict__ Bh, const __half* __restrict__ Bl,
    float* __restrict__ Cf,
    int K, int N, long sCz,
    const int* __restrict__ aOff, const int* __restrict__ aCnt,
    const int* __restrict__ bOff, const int* __restrict__ bCnt)
{
    extern __shared__ char smraw[];
    const uint32_t sb = smem_u32(smraw);
    const int tid = threadIdx.x;
    const int wid = tid >> 5;
    const int l   = tid & 31;

    const int bz = blockIdx.z;
    const long m0 = (long)blockIdx.y * 128;
    const long n0 = (long)blockIdx.x * 128;
    if (m0 >= aCnt[bz]) return;
    if (n0 >= bCnt[bz]) return;
    const long abase = aOff[bz];
    const long bbase = bOff[bz];
    Cf += (long)bz * sCz;

    const int lr_ = tid >> 2;
    const int lc_ = tid & 3;
    const __half* gAh = Ah + (abase + m0 + lr_) * (long)K + lc_ * 8;
    const __half* gAl = Al + (abase + m0 + lr_) * (long)K + lc_ * 8;
    const __half* gBh = Bh + (bbase + n0 + lr_) * (long)K + lc_ * 8;
    const __half* gBl = Bl + (bbase + n0 + lr_) * (long)K + lc_ * 8;

    GEMM_MAINLOOP(gAh, gAl, gBh, gBl, K)

    const int tm = l >> 2;
    const int tn = (l & 3) * 2;
#pragma unroll
    for (int mt = 0; mt < 2; mt++) {
        const long r0 = m0 + warpM + mt * 16 + tm;
        const long r1 = r0 + 8;
#pragma unroll
        for (int nt = 0; nt < 4; nt++) {
            const long col = n0 + warpN + nt * 8 + tn;
            float2 x01 = __half22float2(*(__half2*)&accx[mt][nt][0]);
            float2 x23 = __half22float2(*(__half2*)&accx[mt][nt][1]);
            *(float2*)(Cf + r0 * (long)N + col) =
                make_float2(acc[mt][nt][0] + x01.x, acc[mt][nt][1] + x01.y);
            *(float2*)(Cf + r1 * (long)N + col) =
                make_float2(acc[mt][nt][2] + x23.x, acc[mt][nt][3] + x23.y);
        }
    }
}

// ---------------------------------------------------------------------------
// Softmax over compacted cols + scatter to full output (exact vs reference).
// ---------------------------------------------------------------------------
__global__ void __launch_bounds__(256) softmax_scatter_kernel(
    const float* __restrict__ logc,
    const int* __restrict__ qidx, const int* __restrict__ kidx,
    const int* __restrict__ qcnt, const int* __restrict__ kcnt,
    float* __restrict__ out)
{
    const int b = blockIdx.y;
    const int i = blockIdx.x;
    const int tid = threadIdx.x;
    const int qc = qcnt[b];
    const int orow = qidx[b * 1024 + i];
    float* dst = out + ((long)b * 1024 + orow) * 1024;

    if (i >= qc) {
        ((float4*)dst)[tid] = make_float4(0.f, 0.f, 0.f, 0.f);
        return;
    }

    const int kc = kcnt[b];
    const float* src = logc + ((long)b * 1024 + i) * 1024;
    const int j0 = tid * 4;

    __shared__ float row[1024];
    __shared__ float red[8];

    float4 v = ((const float4*)src)[tid];
    float x0 = (j0 + 0 < kc) ? v.x : -1e30f;
    float x1 = (j0 + 1 < kc) ? v.y : -1e30f;
    float x2 = (j0 + 2 < kc) ? v.z : -1e30f;
    float x3 = (j0 + 3 < kc) ? v.w : -1e30f;

    float mx = fmaxf(fmaxf(x0, x1), fmaxf(x2, x3));
#pragma unroll
    for (int o = 16; o > 0; o >>= 1)
        mx = fmaxf(mx, __shfl_xor_sync(0xFFFFFFFFu, mx, o));
    if ((tid & 31) == 0) red[tid >> 5] = mx;
    __syncthreads();
    float bmx = red[0];
#pragma unroll
    for (int w = 1; w < 8; w++) bmx = fmaxf(bmx, red[w]);
    __syncthreads();

    float e0 = expf(x0 - bmx);
    float e1 = expf(x1 - bmx);
    float e2 = expf(x2 - bmx);
    float e3 = expf(x3 - bmx);
    float s = e0 + e1 + e2 + e3;
#pragma unroll
    for (int o = 16; o > 0; o >>= 1)
        s += __shfl_xor_sync(0xFFFFFFFFu, s, o);
    if ((tid & 31) == 0) red[tid >> 5] = s;
    __syncthreads();
    float bs = 0.0f;
#pragma unroll
    for (int w = 0; w < 8; w++) bs += red[w];
    const float inv = 1.0f / bs;

    ((float4*)row)[tid] = make_float4(0.f, 0.f, 0.f, 0.f);
    __syncthreads();
    const int* kix = kidx + b * 1024;
    if (j0 + 0 < kc) row[kix[j0 + 0]] = e0 * inv;
    if (j0 + 1 < kc) row[kix[j0 + 1]] = e1 * inv;
    if (j0 + 2 < kc) row[kix[j0 + 2]] = e2 * inv;
    if (j0 + 3 < kc) row[kix[j0 + 3]] = e3 * inv;
    __syncthreads();

    ((float4*)dst)[tid] = ((float4*)row)[tid];
}

// ---------------------------------------------------------------------------
// kernel_launch
// ---------------------------------------------------------------------------
extern "C" void kernel_launch(void* const* d_in, const int* in_sizes, int n_in,
                              void* d_out, int out_size)
{
    const float* query = (const float*)d_in[0];
    const float* key   = (const float*)d_in[1];
    const int*   qmask = (const int*)  d_in[2];
    const int*   kmask = (const int*)  d_in[3];
    const float* Wq    = (const float*)d_in[4];
    const float* bq    = (const float*)d_in[5];
    const float* Wk    = (const float*)d_in[6];
    const float* bk    = (const float*)d_in[7];
    float* out = (float*)d_out;

    __half *qh, *ql, *kh, *kl, *wqh, *wql, *wkh, *wkl;
    __half *qph, *qpl, *kph, *kpl;
    float* logc;
    int *qidx, *kidx, *qcnt, *kcnt, *qoff, *koff;
    cudaGetSymbolAddress((void**)&qh,   g_qh);
    cudaGetSymbolAddress((void**)&ql,   g_ql);
    cudaGetSymbolAddress((void**)&kh,   g_kh);
    cudaGetSymbolAddress((void**)&kl,   g_kl);
    cudaGetSymbolAddress((void**)&wqh,  g_wqh);
    cudaGetSymbolAddress((void**)&wql,  g_wql);
    cudaGetSymbolAddress((void**)&wkh,  g_wkh);
    cudaGetSymbolAddress((void**)&wkl,  g_wkl);
    cudaGetSymbolAddress((void**)&qph,  g_qph);
    cudaGetSymbolAddress((void**)&qpl,  g_qpl);
    cudaGetSymbolAddress((void**)&kph,  g_kph);
    cudaGetSymbolAddress((void**)&kpl,  g_kpl);
    cudaGetSymbolAddress((void**)&logc, g_logc);
    cudaGetSymbolAddress((void**)&qidx, g_qidx);
    cudaGetSymbolAddress((void**)&kidx, g_kidx);
    cudaGetSymbolAddress((void**)&qcnt, g_qcnt);
    cudaGetSymbolAddress((void**)&kcnt, g_kcnt);
    cudaGetSymbolAddress((void**)&qoff, g_qoff);
    cudaGetSymbolAddress((void**)&koff, g_koff);

    cudaFuncSetAttribute(gemm_proj_dual_kernel,
                         cudaFuncAttributeMaxDynamicSharedMemorySize, SMEM_BYTES);
    cudaFuncSetAttribute(gemm_logits_kernel,
                         cudaFuncAttributeMaxDynamicSharedMemorySize, SMEM_BYTES);

    // Mask partition + global offsets
    mask_scan_kernel<<<BATCH, 1024>>>(qmask, kmask, qidx, kidx, qcnt, kcnt);
    offsets_kernel<<<1, 32>>>(qcnt, kcnt, qoff, koff);

    // Merged gather-split (q & k in one launch, grid.z = 2)
    dim3 gsg(LQ, BATCH, 2);
    split_gather2_kernel<<<gsg, 256>>>(
        query, qidx, qcnt, qoff, qh, ql,
        key,   kidx, kcnt, koff, kh, kl);
    // Weights
    dim3 gs_w((unsigned)((WN / 4) / 256), 2);
    split_kernel<<<gs_w, 256>>>(Wq, wqh, wql, Wk, wkh, wkl, (int)(WN / 4));

    // Merged projections (q & k in one launch, grid.z = 2)
    dim3 gproj(HID / 128, (BATCH * LQ) / 128, 2);   // (8, 256, 2)
    gemm_proj_dual_kernel<<<gproj, 512, SMEM_BYTES>>>(
        qh, ql, wqh, wql, bq, qph, qpl, qoff + BATCH,
        kh, kl, wkh, wkl, bk, kph, kpl, koff + BATCH,
        KDIM, HID);

    // Batched compacted logits
    dim3 glog(LK / 128, LQ / 128, BATCH);
    gemm_logits_kernel<<<glog, 512, SMEM_BYTES>>>(
        qph, qpl, kph, kpl, logc,
        HID, LK, (long)LQ * LK, qoff, qcnt, koff, kcnt);

    // Softmax + scatter
    dim3 gsm(LQ, BATCH);
    softmax_scatter_kernel<<<gsm, 256>>>(logc, qidx, kidx, qcnt, kcnt, out);
}